// round 12
// baseline (speedup 1.0000x reference)
#include <cuda_runtime.h>
#include <cuda_bf16.h>
#include <math.h>

#define Bsz 1024
#define Nn  63
#define Rr  (Bsz*Nn)      // 64512
#define HID 128
#define G3  384
#define XK  512
#define BMV 1000

#define SMW 36            // words per smem row (32 data words = 64 bf16 + 4 pad)
#define TILEW (128*SMW)   // words per 128-row tile
#define DSMEM_BYTES (4*TILEW*4)   // 2 buffers x (A+B) tiles = 72KB
#define PRED_SMEM ((64*SMW + TILEW)*4)  // A(64 rows) + B(128 rows) = 27648B
#define GH_SMEM (2*TILEW*4)       // 1 buffer x (A+B) = 36KB

// ---------------- aliased scratch pool (phase-disjoint lifetimes) ----------------
#define OFF_GI  ((size_t)0)
#define OFF_GH  ((size_t)132120576)
#define OFF_XB  ((size_t)261144576)
#define OFF_H   ((size_t)327204864)
#define POOL_BYTES ((size_t)360235008)

__device__ __align__(128) unsigned char g_pool[POOL_BYTES];

#define PTR_GI  ((float*)(g_pool + OFF_GI))
#define PTR_GH  ((float*)(g_pool + OFF_GH))
#define PTR_XB  ((__nv_bfloat16*)(g_pool + OFF_XB))
#define PTR_H   ((float*)(g_pool + OFF_H))

__device__ __align__(16) float g_WopT [96*128];
__device__ __align__(16) __nv_bfloat16 g_Wpb  [128*64];
__device__ __align__(16) __nv_bfloat16 g_Wbmb [128*BMV];
__device__ __align__(16) __nv_bfloat16 g_Wihb [G3*XK];
__device__ __align__(16) __nv_bfloat16 g_Whhb [G3*HID];
__device__ int g_levels[8*32];
__device__ int g_levcnt[8];

// ---------------- prep: transpose Wop (fp32) + convert weights to bf16 ----------------
__global__ void k_prep(const float* __restrict__ Wop, const float* __restrict__ Wpred,
                       const float* __restrict__ Wbm, const float* __restrict__ Wih,
                       const float* __restrict__ Whh) {
    int i = blockIdx.x * blockDim.x + threadIdx.x;
    if (i < 128*96) { int r=i/96, c=i-r*96; g_WopT[c*128+r] = Wop[i]; return; }
    i -= 128*96;
    if (i < 128*64)   { g_Wpb[i]   = __float2bfloat16(Wpred[i]); return; }
    i -= 128*64;
    if (i < 128*BMV)  { g_Wbmb[i]  = __float2bfloat16(Wbm[i]);   return; }
    i -= 128*BMV;
    if (i < G3*XK)    { g_Wihb[i]  = __float2bfloat16(Wih[i]);   return; }
    i -= G3*XK;
    if (i < G3*HID)   { g_Whhb[i]  = __float2bfloat16(Whh[i]);   return; }
}

__global__ void k_depth(const int* __restrict__ li) {
    if (threadIdx.x == 0 && blockIdx.x == 0) {
        int depth[Nn];
        for (int d = 0; d < 8; d++) g_levcnt[d] = 0;
        for (int i = 0; i < Nn; i++) {
            int l = li[i];
            depth[i] = (l < 0) ? 1 : (depth[l] + 1);
            int d = depth[i];
            g_levels[d*32 + g_levcnt[d]] = i;
            g_levcnt[d]++;
        }
    }
}

// ================= bf16 MMA machinery =================
__device__ __forceinline__ unsigned pack2(float lo, float hi) {
    __nv_bfloat162 h = __floats2bfloat162_rn(lo, hi);
    return *(unsigned*)&h;
}

__device__ __forceinline__ void mma_bf16(float c[4], unsigned a0, unsigned a1,
                                         unsigned a2, unsigned a3,
                                         unsigned b0, unsigned b1) {
    asm volatile("mma.sync.aligned.m16n8k16.row.col.f32.bf16.bf16.f32 "
                 "{%0,%1,%2,%3}, {%4,%5,%6,%7}, {%8,%9}, {%0,%1,%2,%3};"
                 : "+f"(c[0]), "+f"(c[1]), "+f"(c[2]), "+f"(c[3])
                 : "r"(a0), "r"(a1), "r"(a2), "r"(a3), "r"(b0), "r"(b1));
}

__device__ __forceinline__ void ldsm4(unsigned addr, unsigned &r0, unsigned &r1,
                                      unsigned &r2, unsigned &r3) {
    asm volatile("ldmatrix.sync.aligned.m8n8.x4.shared.b16 {%0,%1,%2,%3}, [%4];"
                 : "=r"(r0), "=r"(r1), "=r"(r2), "=r"(r3) : "r"(addr));
}

__device__ __forceinline__ void cp16(unsigned dst, const void* src, int src_bytes) {
    asm volatile("cp.async.cg.shared.global [%0], [%1], 16, %2;\n"
                 :: "r"(dst), "l"(src), "r"(src_bytes));
}
__device__ __forceinline__ void cp_commit() {
    asm volatile("cp.async.commit_group;\n" ::: "memory");
}
template<int N> __device__ __forceinline__ void cp_wait() {
    asm volatile("cp.async.wait_group %0;\n" :: "n"(N) : "memory");
}

// per-lane ldmatrix byte offsets within a tile
__device__ __forceinline__ void frag_offs(int lane, int wm, int wn,
                                          unsigned aoff[2], unsigned boff[4]) {
    int g = lane >> 3, ri = lane & 7;
#pragma unroll
    for (int mt = 0; mt < 2; mt++) {
        int row = wm*32 + mt*16 + (g & 1)*8 + ri;
        aoff[mt] = row * (SMW*4) + (g >> 1) * 16;
    }
#pragma unroll
    for (int p = 0; p < 4; p++) {
        int row = wn*64 + p*16 + (g >> 1)*8 + ri;
        boff[p] = row * (SMW*4) + (g & 1) * 16;
    }
}

// consume one 64-k chunk: 4 k16 steps
__device__ __forceinline__ void mma_chunk(unsigned abase, unsigned bbase,
                                          const unsigned aoff[2], const unsigned boff[4],
                                          float c[2][8][4]) {
#pragma unroll
    for (int ks = 0; ks < 4; ks++) {
        unsigned a[2][4];
#pragma unroll
        for (int mt = 0; mt < 2; mt++)
            ldsm4(abase + aoff[mt] + ks*32, a[mt][0], a[mt][1], a[mt][2], a[mt][3]);
#pragma unroll
        for (int p = 0; p < 4; p++) {
            unsigned b0, b1, b2, b3;
            ldsm4(bbase + boff[p] + ks*32, b0, b1, b2, b3);
            mma_bf16(c[0][2*p],   a[0][0], a[0][1], a[0][2], a[0][3], b0, b1);
            mma_bf16(c[1][2*p],   a[1][0], a[1][1], a[1][2], a[1][3], b0, b1);
            mma_bf16(c[0][2*p+1], a[0][0], a[0][1], a[0][2], a[0][3], b2, b3);
            mma_bf16(c[1][2*p+1], a[1][0], a[1][1], a[1][2], a[1][3], b2, b3);
        }
    }
}

// async stage: 128 rows x 64 k (bf16 source) via cp.async
__device__ __forceinline__ void stage_async(unsigned sbase,
                                            const __nv_bfloat16* __restrict__ A,
                                            int ld, int rbase, int kt, int Ktot, int t) {
    const int row = t >> 1;
    const int seg0 = (t & 1) * 4;
    const __nv_bfloat16* rowp = A + (size_t)(rbase + row) * ld;
#pragma unroll
    for (int i = 0; i < 4; i++) {
        int k0 = kt + (seg0 + i) * 8;
        int sb = (Ktot - k0) * 2;
        sb = sb < 0 ? 0 : (sb > 16 ? 16 : sb);
        cp16(sbase + row*(SMW*4) + (seg0 + i)*16, rowp + (sb > 0 ? k0 : 0), sb);
    }
}

// register stage: 64 rows of fp32 (full 64-k), packed to bf16
__device__ __forceinline__ void stage_f32_64(unsigned* S, const float* __restrict__ A,
                                             int ld, int rbase, int t) {
    const int tr = t >> 3, wg = t & 7;
#pragma unroll
    for (int p = 0; p < 2; p++) {
        int row = p * 32 + tr;
        size_t off = (size_t)(rbase + row) * ld + wg * 8;
        float4 v0 = *(const float4*)(A + off);
        float4 v1 = *(const float4*)(A + off + 4);
        uint4 w;
        w.x = pack2(v0.x, v0.y); w.y = pack2(v0.z, v0.w);
        w.z = pack2(v1.x, v1.y); w.w = pack2(v1.z, v1.w);
        *(uint4*)&S[row * SMW + wg * 4] = w;
    }
}

// register stage: 128 rows of fp32, packed to bf16 words, k-guarded
__device__ __forceinline__ void stage_f32(unsigned* S, const float* __restrict__ A,
                                          int ld, int rbase, int kt, int Ktot, int t) {
    const int tr = t >> 3, wg = t & 7;
#pragma unroll
    for (int p = 0; p < 4; p++) {
        int row = p * 32 + tr;
        size_t off = (size_t)(rbase + row) * ld + kt + wg * 8;
        int k0 = kt + wg * 8;
        uint4 w;
        if (k0 + 8 <= Ktot) {
            float4 v0 = *(const float4*)(A + off);
            float4 v1 = *(const float4*)(A + off + 4);
            w.x = pack2(v0.x, v0.y); w.y = pack2(v0.z, v0.w);
            w.z = pack2(v1.x, v1.y); w.w = pack2(v1.z, v1.w);
        } else {
            float f[8];
#pragma unroll
            for (int i = 0; i < 8; i++)
                f[i] = (k0 + i < Ktot) ? A[off + i] : 0.f;
            w.x = pack2(f[0], f[1]); w.y = pack2(f[2], f[3]);
            w.z = pack2(f[4], f[5]); w.w = pack2(f[6], f[7]);
        }
        *(uint4*)&S[row * SMW + wg * 4] = w;
    }
}

// register stage: 128 rows of fp32 avg(A,A2), packed bf16 (full 64-k chunk)
__device__ __forceinline__ void stage_f32avg(unsigned* S, const float* __restrict__ A,
                                             const float* __restrict__ A2,
                                             int ld, int rbase, int kt, int t) {
    const int tr = t >> 3, wg = t & 7;
#pragma unroll
    for (int p = 0; p < 4; p++) {
        int row = p * 32 + tr;
        size_t off = (size_t)(rbase + row) * ld + kt + wg * 8;
        float4 v0 = *(const float4*)(A + off);
        float4 v1 = *(const float4*)(A + off + 4);
        float4 u0 = *(const float4*)(A2 + off);
        float4 u1 = *(const float4*)(A2 + off + 4);
        uint4 w;
        w.x = pack2(0.5f*(v0.x+u0.x), 0.5f*(v0.y+u0.y));
        w.y = pack2(0.5f*(v0.z+u0.z), 0.5f*(v0.w+u0.w));
        w.z = pack2(0.5f*(v1.x+u1.x), 0.5f*(v1.y+u1.y));
        w.w = pack2(0.5f*(v1.z+u1.z), 0.5f*(v1.w+u1.w));
        *(uint4*)&S[row * SMW + wg * 4] = w;
    }
}

// copy stage for bf16 weights (full 64-k chunks only)
__device__ __forceinline__ void stage_copy(unsigned* S, const __nv_bfloat16* __restrict__ B,
                                           int ld, int rbase, int kt, int t) {
    const int row = t >> 1;
    const int seg0 = (t & 1) * 4;
    const __nv_bfloat16* rowp = B + (size_t)(rbase + row) * ld + kt;
#pragma unroll
    for (int i = 0; i < 4; i++)
        *(uint4*)&S[row * SMW + (seg0 + i) * 4] = *(const uint4*)(rowp + (seg0 + i) * 8);
}

// mainloop: both operands bf16, cp.async double-buffered
__device__ __forceinline__ void mm_async(const __nv_bfloat16* __restrict__ A, int lda,
                                         const __nv_bfloat16* __restrict__ B, int ldb,
                                         int Ktot, int rbase, int cbase,
                                         unsigned* SM, int t, int wm, int wn, int lane,
                                         float c[2][8][4]) {
#pragma unroll
    for (int mt = 0; mt < 2; mt++)
#pragma unroll
        for (int nt = 0; nt < 8; nt++)
#pragma unroll
            for (int j = 0; j < 4; j++) c[mt][nt][j] = 0.f;

    const unsigned sm0 = (unsigned)__cvta_generic_to_shared(SM);
    const unsigned TB = TILEW * 4;
    const int nc = (Ktot + 63) >> 6;
    unsigned aoff[2], boff[4];
    frag_offs(lane, wm, wn, aoff, boff);

    stage_async(sm0, A, lda, rbase, 0, Ktot, t);
    stage_async(sm0 + TB, B, ldb, cbase, 0, Ktot, t);
    cp_commit();

    for (int ch = 0; ch < nc; ch++) {
        unsigned abase = sm0 + (unsigned)(ch & 1) * 2 * TB;
        unsigned bbase = abase + TB;
        if (ch + 1 < nc) {
            unsigned na = sm0 + (unsigned)((ch + 1) & 1) * 2 * TB;
            stage_async(na, A, lda, rbase, (ch + 1) << 6, Ktot, t);
            stage_async(na + TB, B, ldb, cbase, (ch + 1) << 6, Ktot, t);
            cp_commit();
            cp_wait<1>();
        } else {
            cp_wait<0>();
        }
        __syncthreads();
        mma_chunk(abase, bbase, aoff, boff, c);
        __syncthreads();
    }
}

// mainloop: A fp32 (register-staged, fused convert), B bf16 (cp.async), double-buffered
__device__ __forceinline__ void mm_f32A(const float* __restrict__ A, int lda,
                                        const __nv_bfloat16* __restrict__ B, int ldb,
                                        int Ktot, int rbase, int cbase,
                                        unsigned* SM, int t, int wm, int wn, int lane,
                                        float c[2][8][4]) {
#pragma unroll
    for (int mt = 0; mt < 2; mt++)
#pragma unroll
        for (int nt = 0; nt < 8; nt++)
#pragma unroll
            for (int j = 0; j < 4; j++) c[mt][nt][j] = 0.f;

    const unsigned sm0 = (unsigned)__cvta_generic_to_shared(SM);
    const unsigned TB = TILEW * 4;
    const int nc = (Ktot + 63) >> 6;
    unsigned aoff[2], boff[4];
    frag_offs(lane, wm, wn, aoff, boff);

    stage_async(sm0 + TB, B, ldb, cbase, 0, Ktot, t);   // B0
    cp_commit();
    stage_f32(SM, A, lda, rbase, 0, Ktot, t);           // A0 (regs->STS)

    for (int ch = 0; ch < nc; ch++) {
        unsigned abase = sm0 + (unsigned)(ch & 1) * 2 * TB;
        unsigned bbase = abase + TB;
        if (ch + 1 < nc) {
            unsigned na = sm0 + (unsigned)((ch + 1) & 1) * 2 * TB;
            stage_async(na + TB, B, ldb, cbase, (ch + 1) << 6, Ktot, t);
            cp_commit();
            cp_wait<1>();   // B(ch) landed
        } else {
            cp_wait<0>();
        }
        __syncthreads();    // A(ch) STS visible, buffers free
        mma_chunk(abase, bbase, aoff, boff, c);
        __syncthreads();    // consumption done before next STS overwrites
        if (ch + 1 < nc) {
            unsigned* nA = (unsigned*)SM + (((ch + 1) & 1) ? 2*TILEW : 0);
            stage_f32(nA, A, lda, rbase, (ch + 1) << 6, Ktot, t);
        }
    }
}

// ---------------- pred: m-split (64 rows x 128 cols), fused fp32->bf16 A, min over P=8 ----------------
__global__ __launch_bounds__(256) void k_pred_mma(const float* __restrict__ p1,
                                                  const float* __restrict__ p2,
                                                  const int* __restrict__ c1p,
                                                  const int* __restrict__ c2p,
                                                  const float* __restrict__ bpred) {
    extern __shared__ unsigned dsm[];
    const float* preds = blockIdx.y ? p2 : p1;
    const int* cond = blockIdx.y ? c2p : c1p;
    const int xoff = blockIdx.y ? 256 : 128;
    const int t = threadIdx.x, lane = t & 31, warp = t >> 5;
    const int wmq = warp >> 1, wn = warp & 1;   // 4 m-tiles x 2 n-halves
    const int rbase = blockIdx.x * 64;
    const int qc = lane & 3;
    const int g8 = lane >> 3, ri8 = lane & 7;

    const unsigned sm0 = (unsigned)__cvta_generic_to_shared(dsm);
    const unsigned bb0 = sm0 + 64 * SMW * 4;    // B region after 64 A rows

    unsigned aoff = (wmq*16 + (g8 & 1)*8 + ri8) * (SMW*4) + (g8 >> 1) * 16;
    unsigned boff[4];
#pragma unroll
    for (int p = 0; p < 4; p++)
        boff[p] = (wn*64 + p*16 + (g8 >> 1)*8 + ri8) * (SMW*4) + (g8 & 1) * 16;

    stage_async(bb0, g_Wpb, 64, 0, 0, 64, t);   // B: all 128 weight rows
    cp_commit();
    stage_f32_64(dsm, preds, 64, rbase, t);     // A: 64 rows fused fp32->bf16
    cp_wait<0>();
    __syncthreads();

    float c[8][4];
#pragma unroll
    for (int nt = 0; nt < 8; nt++)
#pragma unroll
        for (int j = 0; j < 4; j++) c[nt][j] = 0.f;

#pragma unroll
    for (int ks = 0; ks < 4; ks++) {
        unsigned a0, a1, a2, a3;
        ldsm4(sm0 + aoff + ks*32, a0, a1, a2, a3);
#pragma unroll
        for (int p = 0; p < 4; p++) {
            unsigned b0, b1, b2, b3;
            ldsm4(bb0 + boff[p] + ks*32, b0, b1, b2, b3);
            mma_bf16(c[2*p],   a0, a1, a2, a3, b0, b1);
            mma_bf16(c[2*p+1], a0, a1, a2, a3, b2, b3);
        }
    }

#pragma unroll
    for (int nt = 0; nt < 8; nt++)
#pragma unroll
        for (int j = 0; j < 4; j++) {
            float v = c[nt][j];
            v = fminf(v, __shfl_xor_sync(0xffffffffu, v, 4));
            v = fminf(v, __shfl_xor_sync(0xffffffffu, v, 8));
            v = fminf(v, __shfl_xor_sync(0xffffffffu, v, 16));
            c[nt][j] = v;
        }
    if (lane < 4) {
        int or0 = (rbase + wmq * 16) >> 3;
        float cnd0 = (float)cond[or0];
        float cnd1 = (float)cond[or0 + 1];
#pragma unroll
        for (int nt = 0; nt < 8; nt++) {
            int col = wn * 64 + nt * 8 + qc * 2;
            float b0 = bpred[col], b1 = bpred[col + 1];
            unsigned w0 = pack2((c[nt][0] + b0) * cnd0, (c[nt][1] + b1) * cnd0);
            *(unsigned*)&PTR_XB[(size_t)or0 * XK + xoff + col] = w0;
            unsigned w1 = pack2((c[nt][2] + b0) * cnd1, (c[nt][3] + b1) * cnd1);
            *(unsigned*)&PTR_XB[(size_t)(or0 + 1) * XK + xoff + col] = w1;
        }
    }
}

// ---------------- bitmap: fused fp32->bf16 A-staging ----------------
__global__ __launch_bounds__(256) void k_bm_mma(const float* __restrict__ bm,
                                                const float* __restrict__ bbm,
                                                const int* __restrict__ hc) {
    extern __shared__ unsigned dsm[];
    const int t = threadIdx.x, lane = t & 31, warp = t >> 5;
    const int wm = warp >> 1, wn = warp & 1;
    const int rbase = blockIdx.x * 128;
    float c[2][8][4];
    mm_f32A(bm, BMV, g_Wbmb, BMV, BMV, rbase, 0, dsm, t, wm, wn, lane, c);

    const int qr = lane >> 2, qc = lane & 3;
#pragma unroll
    for (int mt = 0; mt < 2; mt++)
#pragma unroll
        for (int h = 0; h < 2; h++) {
            int r = rbase + wm * 32 + mt * 16 + qr + h * 8;
            float has = (float)hc[r];
#pragma unroll
            for (int nt = 0; nt < 8; nt++) {
                int col = wn * 64 + nt * 8 + qc * 2;
                unsigned w = pack2((c[mt][nt][2*h]   + bbm[col])   * has,
                                   (c[mt][nt][2*h+1] + bbm[col+1]) * has);
                *(unsigned*)&PTR_XB[(size_t)r * XK + 384 + col] = w;
            }
        }
}

// ---------------- gi (bf16 x from pool) ----------------
__global__ __launch_bounds__(256) void k_gi_mma(const float* __restrict__ bih) {
    extern __shared__ unsigned dsm[];
    const int t = threadIdx.x, lane = t & 31, warp = t >> 5;
    const int wm = warp >> 1, wn = warp & 1;
    const int rbase = blockIdx.x * 128;
    const int cbase = blockIdx.y * 128;
    float c[2][8][4];
    mm_async(PTR_XB, XK, g_Wihb, XK, XK, rbase, cbase, dsm, t, wm, wn, lane, c);

    const int qr = lane >> 2, qc = lane & 3;
#pragma unroll
    for (int mt = 0; mt < 2; mt++)
#pragma unroll
        for (int h = 0; h < 2; h++) {
            int r = rbase + wm * 32 + mt * 16 + qr + h * 8;
            int n = r % Nn, b = r / Nn;
            size_t obase = ((size_t)n * Bsz + b) * G3;
#pragma unroll
            for (int nt = 0; nt < 8; nt++) {
                int g = cbase + wn * 64 + nt * 8 + qc * 2;
                float2 w = make_float2(c[mt][nt][2*h] + bih[g],
                                       c[mt][nt][2*h+1] + bih[g+1]);
                *(float2*)&PTR_GI[obase + g] = w;
            }
        }
}

// ---------------- gh: per-level gh[node][b][g] = 0.5(Hl+Hr) @ Whh^T ----------------
__global__ __launch_bounds__(256) void k_gh_mma(const int* __restrict__ li,
                                                const int* __restrict__ ri,
                                                int level) {
    extern __shared__ unsigned dsm[];
    const int slot = blockIdx.z;
    if (slot >= g_levcnt[level]) return;
    const int node = g_levels[level*32 + slot];
    const int l = li[node], r = ri[node];
    const int t = threadIdx.x, lane = t & 31, warp = t >> 5;
    const int wm = warp >> 1, wn = warp & 1;
    const int rbase = blockIdx.x * 128;
    const int cbase = blockIdx.y * 128;
    const float* Hl = PTR_H + (size_t)l * Bsz * HID;
    const float* Hr = PTR_H + (size_t)r * Bsz * HID;

    float c[2][8][4];
#pragma unroll
    for (int mt = 0; mt < 2; mt++)
#pragma unroll
        for (int nt = 0; nt < 8; nt++)
#pragma unroll
            for (int j = 0; j < 4; j++) c[mt][nt][j] = 0.f;

    unsigned aoff[2], boff[4];
    frag_offs(lane, wm, wn, aoff, boff);
    const unsigned sm0 = (unsigned)__cvta_generic_to_shared(dsm);
    const unsigned TB = TILEW * 4;

    for (int ch = 0; ch < 2; ch++) {
        stage_f32avg(dsm, Hl, Hr, HID, rbase, ch * 64, t);
        stage_copy(dsm + TILEW, g_Whhb, HID, cbase, ch * 64, t);
        __syncthreads();
        mma_chunk(sm0, sm0 + TB, aoff, boff, c);
        __syncthreads();
    }

    const int qr = lane >> 2, qc = lane & 3;
#pragma unroll
    for (int mt = 0; mt < 2; mt++)
#pragma unroll
        for (int h = 0; h < 2; h++) {
            int b = rbase + wm * 32 + mt * 16 + qr + h * 8;
            size_t obase = ((size_t)node * Bsz + b) * G3;
#pragma unroll
            for (int nt = 0; nt < 8; nt++) {
                int g = cbase + wn * 64 + nt * 8 + qc * 2;
                float2 w = make_float2(c[mt][nt][2*h], c[mt][nt][2*h+1]);
                *(float2*)&PTR_GH[obase + g] = w;
            }
        }
}

// ---------------- gate: elementwise GRU cell per level ----------------
__global__ __launch_bounds__(256) void k_gate(const int* __restrict__ li,
                                              const int* __restrict__ ri,
                                              const float* __restrict__ bhh,
                                              int level) {
    const int slot = blockIdx.y;
    if (slot >= g_levcnt[level]) return;
    const int node = g_levels[level*32 + slot];
    const int l = li[node], r = ri[node];
    const int idx = blockIdx.x * 256 + threadIdx.x;
    const int b = idx >> 7, g = idx & 127;
    const size_t gib = ((size_t)node * Bsz + b) * G3;
    const float br = bhh[g], bz = bhh[128+g], bn = bhh[256+g];
    float hv, ghr, ghz, ghn;
    if (l < 0) {
        hv = 0.f; ghr = br; ghz = bz; ghn = bn;
    } else {
        hv = 0.5f * (PTR_H[(size_t)l*Bsz*HID + b*HID + g] + PTR_H[(size_t)r*Bsz*HID + b*HID + g]);
        ghr = PTR_GH[gib + g] + br;
        ghz = PTR_GH[gib + 128 + g] + bz;
        ghn = PTR_GH[gib + 256 + g] + bn;
    }
    float rg = 1.f/(1.f + expf(-(PTR_GI[gib + g] + ghr)));
    float zg = 1.f/(1.f + expf(-(PTR_GI[gib + 128 + g] + ghz)));
    float ng = tanhf(PTR_GI[gib + 256 + g] + rg * ghn);
    PTR_H[((size_t)node * Bsz + b) * HID + g] = (1.f - zg) * ng + zg * hv;
}

// ---------------- opemb (fp32, small) -> bf16 x ----------------
__global__ __launch_bounds__(256) void k_opemb(const float* __restrict__ op,
                                               const float* __restrict__ ex,
                                               const float* __restrict__ bop) {
    __shared__ float As[16][68];
    __shared__ float Bs[16][128];
    const int t = threadIdx.x;
    const int rbase = blockIdx.x * 64;
    const int ty = t >> 5, tx = t & 31;
    const int row0 = ty * 8, col0 = tx * 4;
    float acc[8][4];
#pragma unroll
    for (int i = 0; i < 8; i++)
#pragma unroll
        for (int j = 0; j < 4; j++) acc[i][j] = 0.f;

    for (int kt = 0; kt < 96; kt += 16) {
#pragma unroll
        for (int i = 0; i < 4; i++) {
            int idx = t + i * 256;
            int row = idx >> 4, kk = idx & 15;
            int k = kt + kk;
            As[kk][row] = (k < 32) ? op[(size_t)(rbase+row)*32 + k]
                                   : ex[(size_t)(rbase+row)*64 + (k-32)];
        }
#pragma unroll
        for (int i = 0; i < 8; i++) {
            int idx = t + i * 256;
            int kk = idx >> 7, c = idx & 127;
            Bs[kk][c] = g_WopT[(kt+kk)*128 + c];
        }
        __syncthreads();
#pragma unroll
        for (int kk = 0; kk < 16; kk++) {
            float4 a0 = *(const float4*)&As[kk][row0];
            float4 a1 = *(const float4*)&As[kk][row0+4];
            float4 b  = *(const float4*)&Bs[kk][col0];
            float a[8] = {a0.x,a0.y,a0.z,a0.w,a1.x,a1.y,a1.z,a1.w};
            float bb[4]= {b.x,b.y,b.z,b.w};
#pragma unroll
            for (int i = 0; i < 8; i++)
#pragma unroll
                for (int j = 0; j < 4; j++) acc[i][j] += a[i]*bb[j];
        }
        __syncthreads();
    }
#pragma unroll
    for (int i = 0; i < 8; i++) {
        int r = rbase + row0 + i;
#pragma unroll
        for (int j = 0; j < 4; j += 2) {
            unsigned w = pack2(acc[i][j] + bop[col0+j], acc[i][j+1] + bop[col0+j+1]);
            *(unsigned*)&PTR_XB[(size_t)r*XK + col0 + j] = w;
        }
    }
}

// ---------------- heads ----------------
__global__ __launch_bounds__(128) void k_heads(const float* __restrict__ W2a, const float* __restrict__ b2a,
                                               const float* __restrict__ W3a, const float* __restrict__ b3a,
                                               const float* __restrict__ Woa, const float* __restrict__ boa,
                                               const float* __restrict__ W2b, const float* __restrict__ b2b,
                                               const float* __restrict__ W3b, const float* __restrict__ b3b,
                                               const float* __restrict__ Wob, const float* __restrict__ bob,
                                               float* __restrict__ out) {
    const int b = blockIdx.x, head = blockIdx.y, t = threadIdx.x;
    const float* W2 = head ? W2b : W2a;  const float* b2 = head ? b2b : b2a;
    const float* W3 = head ? W3b : W3a;  const float* b3 = head ? b3b : b3a;
    const float* Wo = head ? Wob : Woa;  const float* bo = head ? bob : boa;

    __shared__ float s0[128], s1[128], red[4];
    s0[t] = PTR_H[((size_t)(Nn-1)*Bsz + b)*HID + t];
    __syncthreads();
    float acc = b2[t];
#pragma unroll 8
    for (int k = 0; k < 128; k++) acc += s0[k] * W2[t*128 + k];
    s1[t] = fmaxf(acc, 0.f);
    __syncthreads();
    acc = b3[t];
#pragma unroll 8
    for (int k = 0; k < 128; k++) acc += s1[k] * W3[t*128 + k];
    float h2 = fmaxf(acc, 0.f);
    float v = h2 * Wo[t];
#pragma unroll
    for (int off = 16; off; off >>= 1) v += __shfl_down_sync(0xffffffffu, v, off);
    if ((t & 31) == 0) red[t >> 5] = v;
    __syncthreads();
    if (t == 0) {
        float s = red[0] + red[1] + red[2] + red[3] + bo[0];
        out[head * Bsz + b] = 1.f/(1.f + expf(-s));
    }
}

// ---------------- launcher ----------------
extern "C" void kernel_launch(void* const* d_in, const int* in_sizes, int n_in,
                              void* d_out, int out_size) {
    const float* op    = (const float*)d_in[0];
    const float* ex    = (const float*)d_in[1];
    const float* p1    = (const float*)d_in[2];
    const float* p2    = (const float*)d_in[3];
    const int*   c1p   = (const int*)  d_in[4];
    const int*   c2p   = (const int*)  d_in[5];
    const int*   hc    = (const int*)  d_in[6];
    const float* bmp   = (const float*)d_in[7];
    const int*   li    = (const int*)  d_in[8];
    const int*   ri    = (const int*)  d_in[9];
    const float* Wop   = (const float*)d_in[10];
    const float* bop   = (const float*)d_in[11];
    const float* Wpred = (const float*)d_in[12];
    const float* bpred = (const float*)d_in[13];
    const float* Wbm   = (const float*)d_in[14];
    const float* bbm   = (const float*)d_in[15];
    const float* Wih   = (const float*)d_in[16];
    const float* bih   = (const float*)d_in[17];
    const float* Whh   = (const float*)d_in[18];
    const float* bhh   = (const float*)d_in[19];
    const float* W2t1  = (const float*)d_in[20];
    const float* b2t1  = (const float*)d_in[21];
    const float* W3t1  = (const float*)d_in[22];
    const float* b3t1  = (const float*)d_in[23];
    const float* Wot1  = (const float*)d_in[24];
    const float* bot1  = (const float*)d_in[25];
    const float* W2t2  = (const float*)d_in[26];
    const float* b2t2  = (const float*)d_in[27];
    const float* W3t2  = (const float*)d_in[28];
    const float* b3t2  = (const float*)d_in[29];
    const float* Wot2  = (const float*)d_in[30];
    const float* bot2  = (const float*)d_in[31];
    float* out = (float*)d_out;

    cudaFuncSetAttribute(k_pred_mma, cudaFuncAttributeMaxDynamicSharedMemorySize, PRED_SMEM);
    cudaFuncSetAttribute(k_bm_mma,   cudaFuncAttributeMaxDynamicSharedMemorySize, DSMEM_BYTES);
    cudaFuncSetAttribute(k_gi_mma,   cudaFuncAttributeMaxDynamicSharedMemorySize, DSMEM_BYTES);
    cudaFuncSetAttribute(k_gh_mma,   cudaFuncAttributeMaxDynamicSharedMemorySize, GH_SMEM);

    k_prep<<<1540, 256>>>(Wop, Wpred, Wbm, Wih, Whh);
    k_depth<<<1, 1>>>(li);
    k_opemb<<<Rr/64, 256>>>(op, ex, bop);
    k_pred_mma<<<dim3((Rr*8)/64, 2), 256, PRED_SMEM>>>(p1, p2, c1p, c2p, bpred);
    k_bm_mma<<<Rr/128, 256, DSMEM_BYTES>>>(bmp, bbm, hc);
    k_gi_mma<<<dim3(Rr/128, 3), 256, DSMEM_BYTES>>>(bih);
    k_gate<<<dim3(512, 32), 256>>>(li, ri, bhh, 1);
    for (int lvl = 2; lvl <= 6; lvl++) {
        k_gh_mma<<<dim3(8, 3, 16), 256, GH_SMEM>>>(li, ri, lvl);
        k_gate<<<dim3(512, 16), 256>>>(li, ri, bhh, lvl);
    }
    k_heads<<<dim3(Bsz, 2), 128>>>(W2t1, b2t1, W3t1, b3t1, Wot1, bot1,
                                   W2t2, b2t2, W3t2, b3t2, Wot2, bot2, out);
}

// round 13
// speedup vs baseline: 1.0953x; 1.0953x over previous
#include <cuda_runtime.h>
#include <cuda_bf16.h>
#include <math.h>

#define Bsz 1024
#define Nn  63
#define Rr  (Bsz*Nn)      // 64512
#define HID 128
#define G3  384
#define XK  512
#define BMV 1000

#define SMW 36            // words per smem row (32 data words = 64 bf16 + 4 pad)
#define TILEW (128*SMW)   // words per 128-row tile
#define DSMEM_BYTES (4*TILEW*4)   // 2 buffers x (A+B) tiles = 72KB
#define PRED_SMEM (2*TILEW*4)     // A tile + B tile = 36864B
#define GH_SMEM (2*TILEW*4)       // 1 buffer x (A+B) = 36KB

// ---------------- aliased scratch pool (phase-disjoint lifetimes) ----------------
#define OFF_GI  ((size_t)0)
#define OFF_GH  ((size_t)132120576)
#define OFF_XB  ((size_t)261144576)
#define OFF_H   ((size_t)327204864)
#define POOL_BYTES ((size_t)360235008)

__device__ __align__(128) unsigned char g_pool[POOL_BYTES];

#define PTR_GI  ((float*)(g_pool + OFF_GI))
#define PTR_GH  ((float*)(g_pool + OFF_GH))
#define PTR_XB  ((__nv_bfloat16*)(g_pool + OFF_XB))
#define PTR_H   ((float*)(g_pool + OFF_H))

__device__ __align__(16) float g_WopT [96*128];
__device__ __align__(16) __nv_bfloat16 g_Wpb  [128*64];
__device__ __align__(16) __nv_bfloat16 g_Wbmb [128*BMV];
__device__ __align__(16) __nv_bfloat16 g_Wihb [G3*XK];
__device__ __align__(16) __nv_bfloat16 g_Whhb [G3*HID];
__device__ int g_levels[8*32];
__device__ int g_levcnt[8];

// ---------------- prep: transpose Wop (fp32) + convert weights to bf16 ----------------
__global__ void k_prep(const float* __restrict__ Wop, const float* __restrict__ Wpred,
                       const float* __restrict__ Wbm, const float* __restrict__ Wih,
                       const float* __restrict__ Whh) {
    int i = blockIdx.x * blockDim.x + threadIdx.x;
    if (i < 128*96) { int r=i/96, c=i-r*96; g_WopT[c*128+r] = Wop[i]; return; }
    i -= 128*96;
    if (i < 128*64)   { g_Wpb[i]   = __float2bfloat16(Wpred[i]); return; }
    i -= 128*64;
    if (i < 128*BMV)  { g_Wbmb[i]  = __float2bfloat16(Wbm[i]);   return; }
    i -= 128*BMV;
    if (i < G3*XK)    { g_Wihb[i]  = __float2bfloat16(Wih[i]);   return; }
    i -= G3*XK;
    if (i < G3*HID)   { g_Whhb[i]  = __float2bfloat16(Whh[i]);   return; }
}

__global__ void k_depth(const int* __restrict__ li) {
    if (threadIdx.x == 0 && blockIdx.x == 0) {
        int depth[Nn];
        for (int d = 0; d < 8; d++) g_levcnt[d] = 0;
        for (int i = 0; i < Nn; i++) {
            int l = li[i];
            depth[i] = (l < 0) ? 1 : (depth[l] + 1);
            int d = depth[i];
            g_levels[d*32 + g_levcnt[d]] = i;
            g_levcnt[d]++;
        }
    }
}

// ================= bf16 MMA machinery =================
__device__ __forceinline__ unsigned pack2(float lo, float hi) {
    __nv_bfloat162 h = __floats2bfloat162_rn(lo, hi);
    return *(unsigned*)&h;
}

__device__ __forceinline__ void mma_bf16(float c[4], unsigned a0, unsigned a1,
                                         unsigned a2, unsigned a3,
                                         unsigned b0, unsigned b1) {
    asm volatile("mma.sync.aligned.m16n8k16.row.col.f32.bf16.bf16.f32 "
                 "{%0,%1,%2,%3}, {%4,%5,%6,%7}, {%8,%9}, {%0,%1,%2,%3};"
                 : "+f"(c[0]), "+f"(c[1]), "+f"(c[2]), "+f"(c[3])
                 : "r"(a0), "r"(a1), "r"(a2), "r"(a3), "r"(b0), "r"(b1));
}

__device__ __forceinline__ void ldsm4(unsigned addr, unsigned &r0, unsigned &r1,
                                      unsigned &r2, unsigned &r3) {
    asm volatile("ldmatrix.sync.aligned.m8n8.x4.shared.b16 {%0,%1,%2,%3}, [%4];"
                 : "=r"(r0), "=r"(r1), "=r"(r2), "=r"(r3) : "r"(addr));
}

__device__ __forceinline__ void cp16(unsigned dst, const void* src, int src_bytes) {
    asm volatile("cp.async.cg.shared.global [%0], [%1], 16, %2;\n"
                 :: "r"(dst), "l"(src), "r"(src_bytes));
}
__device__ __forceinline__ void cp_commit() {
    asm volatile("cp.async.commit_group;\n" ::: "memory");
}
template<int N> __device__ __forceinline__ void cp_wait() {
    asm volatile("cp.async.wait_group %0;\n" :: "n"(N) : "memory");
}

// per-lane ldmatrix byte offsets within a tile
__device__ __forceinline__ void frag_offs(int lane, int wm, int wn,
                                          unsigned aoff[2], unsigned boff[4]) {
    int g = lane >> 3, ri = lane & 7;
#pragma unroll
    for (int mt = 0; mt < 2; mt++) {
        int row = wm*32 + mt*16 + (g & 1)*8 + ri;
        aoff[mt] = row * (SMW*4) + (g >> 1) * 16;
    }
#pragma unroll
    for (int p = 0; p < 4; p++) {
        int row = wn*64 + p*16 + (g >> 1)*8 + ri;
        boff[p] = row * (SMW*4) + (g & 1) * 16;
    }
}

// consume one 64-k chunk: 4 k16 steps
__device__ __forceinline__ void mma_chunk(unsigned abase, unsigned bbase,
                                          const unsigned aoff[2], const unsigned boff[4],
                                          float c[2][8][4]) {
#pragma unroll
    for (int ks = 0; ks < 4; ks++) {
        unsigned a[2][4];
#pragma unroll
        for (int mt = 0; mt < 2; mt++)
            ldsm4(abase + aoff[mt] + ks*32, a[mt][0], a[mt][1], a[mt][2], a[mt][3]);
#pragma unroll
        for (int p = 0; p < 4; p++) {
            unsigned b0, b1, b2, b3;
            ldsm4(bbase + boff[p] + ks*32, b0, b1, b2, b3);
            mma_bf16(c[0][2*p],   a[0][0], a[0][1], a[0][2], a[0][3], b0, b1);
            mma_bf16(c[1][2*p],   a[1][0], a[1][1], a[1][2], a[1][3], b0, b1);
            mma_bf16(c[0][2*p+1], a[0][0], a[0][1], a[0][2], a[0][3], b2, b3);
            mma_bf16(c[1][2*p+1], a[1][0], a[1][1], a[1][2], a[1][3], b2, b3);
        }
    }
}

// async stage: 128 rows x 64 k (bf16 source) via cp.async
__device__ __forceinline__ void stage_async(unsigned sbase,
                                            const __nv_bfloat16* __restrict__ A,
                                            int ld, int rbase, int kt, int Ktot, int t) {
    const int row = t >> 1;
    const int seg0 = (t & 1) * 4;
    const __nv_bfloat16* rowp = A + (size_t)(rbase + row) * ld;
#pragma unroll
    for (int i = 0; i < 4; i++) {
        int k0 = kt + (seg0 + i) * 8;
        int sb = (Ktot - k0) * 2;
        sb = sb < 0 ? 0 : (sb > 16 ? 16 : sb);
        cp16(sbase + row*(SMW*4) + (seg0 + i)*16, rowp + (sb > 0 ? k0 : 0), sb);
    }
}

// register stage: 128 rows of fp32, packed to bf16 words, k-guarded
__device__ __forceinline__ void stage_f32(unsigned* S, const float* __restrict__ A,
                                          int ld, int rbase, int kt, int Ktot, int t) {
    const int tr = t >> 3, wg = t & 7;
#pragma unroll
    for (int p = 0; p < 4; p++) {
        int row = p * 32 + tr;
        size_t off = (size_t)(rbase + row) * ld + kt + wg * 8;
        int k0 = kt + wg * 8;
        uint4 w;
        if (k0 + 8 <= Ktot) {
            float4 v0 = *(const float4*)(A + off);
            float4 v1 = *(const float4*)(A + off + 4);
            w.x = pack2(v0.x, v0.y); w.y = pack2(v0.z, v0.w);
            w.z = pack2(v1.x, v1.y); w.w = pack2(v1.z, v1.w);
        } else {
            float f[8];
#pragma unroll
            for (int i = 0; i < 8; i++)
                f[i] = (k0 + i < Ktot) ? A[off + i] : 0.f;
            w.x = pack2(f[0], f[1]); w.y = pack2(f[2], f[3]);
            w.z = pack2(f[4], f[5]); w.w = pack2(f[6], f[7]);
        }
        *(uint4*)&S[row * SMW + wg * 4] = w;
    }
}

// register stage: 128 rows of fp32 avg(A,A2), packed bf16 (full 64-k chunk)
__device__ __forceinline__ void stage_f32avg(unsigned* S, const float* __restrict__ A,
                                             const float* __restrict__ A2,
                                             int ld, int rbase, int kt, int t) {
    const int tr = t >> 3, wg = t & 7;
#pragma unroll
    for (int p = 0; p < 4; p++) {
        int row = p * 32 + tr;
        size_t off = (size_t)(rbase + row) * ld + kt + wg * 8;
        float4 v0 = *(const float4*)(A + off);
        float4 v1 = *(const float4*)(A + off + 4);
        float4 u0 = *(const float4*)(A2 + off);
        float4 u1 = *(const float4*)(A2 + off + 4);
        uint4 w;
        w.x = pack2(0.5f*(v0.x+u0.x), 0.5f*(v0.y+u0.y));
        w.y = pack2(0.5f*(v0.z+u0.z), 0.5f*(v0.w+u0.w));
        w.z = pack2(0.5f*(v1.x+u1.x), 0.5f*(v1.y+u1.y));
        w.w = pack2(0.5f*(v1.z+u1.z), 0.5f*(v1.w+u1.w));
        *(uint4*)&S[row * SMW + wg * 4] = w;
    }
}

// copy stage for bf16 weights (full 64-k chunks only)
__device__ __forceinline__ void stage_copy(unsigned* S, const __nv_bfloat16* __restrict__ B,
                                           int ld, int rbase, int kt, int t) {
    const int row = t >> 1;
    const int seg0 = (t & 1) * 4;
    const __nv_bfloat16* rowp = B + (size_t)(rbase + row) * ld + kt;
#pragma unroll
    for (int i = 0; i < 4; i++)
        *(uint4*)&S[row * SMW + (seg0 + i) * 4] = *(const uint4*)(rowp + (seg0 + i) * 8);
}

// mainloop: both operands bf16, cp.async double-buffered
__device__ __forceinline__ void mm_async(const __nv_bfloat16* __restrict__ A, int lda,
                                         const __nv_bfloat16* __restrict__ B, int ldb,
                                         int Ktot, int rbase, int cbase,
                                         unsigned* SM, int t, int wm, int wn, int lane,
                                         float c[2][8][4]) {
#pragma unroll
    for (int mt = 0; mt < 2; mt++)
#pragma unroll
        for (int nt = 0; nt < 8; nt++)
#pragma unroll
            for (int j = 0; j < 4; j++) c[mt][nt][j] = 0.f;

    const unsigned sm0 = (unsigned)__cvta_generic_to_shared(SM);
    const unsigned TB = TILEW * 4;
    const int nc = (Ktot + 63) >> 6;
    unsigned aoff[2], boff[4];
    frag_offs(lane, wm, wn, aoff, boff);

    stage_async(sm0, A, lda, rbase, 0, Ktot, t);
    stage_async(sm0 + TB, B, ldb, cbase, 0, Ktot, t);
    cp_commit();

    for (int ch = 0; ch < nc; ch++) {
        unsigned abase = sm0 + (unsigned)(ch & 1) * 2 * TB;
        unsigned bbase = abase + TB;
        if (ch + 1 < nc) {
            unsigned na = sm0 + (unsigned)((ch + 1) & 1) * 2 * TB;
            stage_async(na, A, lda, rbase, (ch + 1) << 6, Ktot, t);
            stage_async(na + TB, B, ldb, cbase, (ch + 1) << 6, Ktot, t);
            cp_commit();
            cp_wait<1>();
        } else {
            cp_wait<0>();
        }
        __syncthreads();
        mma_chunk(abase, bbase, aoff, boff, c);
        __syncthreads();
    }
}

// mainloop: A fp32 (register-staged, fused convert), B bf16 (cp.async), double-buffered
__device__ __forceinline__ void mm_f32A(const float* __restrict__ A, int lda,
                                        const __nv_bfloat16* __restrict__ B, int ldb,
                                        int Ktot, int rbase, int cbase,
                                        unsigned* SM, int t, int wm, int wn, int lane,
                                        float c[2][8][4]) {
#pragma unroll
    for (int mt = 0; mt < 2; mt++)
#pragma unroll
        for (int nt = 0; nt < 8; nt++)
#pragma unroll
            for (int j = 0; j < 4; j++) c[mt][nt][j] = 0.f;

    const unsigned sm0 = (unsigned)__cvta_generic_to_shared(SM);
    const unsigned TB = TILEW * 4;
    const int nc = (Ktot + 63) >> 6;
    unsigned aoff[2], boff[4];
    frag_offs(lane, wm, wn, aoff, boff);

    stage_async(sm0 + TB, B, ldb, cbase, 0, Ktot, t);   // B0
    cp_commit();
    stage_f32(SM, A, lda, rbase, 0, Ktot, t);           // A0 (regs->STS)

    for (int ch = 0; ch < nc; ch++) {
        unsigned abase = sm0 + (unsigned)(ch & 1) * 2 * TB;
        unsigned bbase = abase + TB;
        if (ch + 1 < nc) {
            unsigned na = sm0 + (unsigned)((ch + 1) & 1) * 2 * TB;
            stage_async(na + TB, B, ldb, cbase, (ch + 1) << 6, Ktot, t);
            cp_commit();
            cp_wait<1>();   // B(ch) landed
        } else {
            cp_wait<0>();
        }
        __syncthreads();    // A(ch) STS visible, buffers free
        mma_chunk(abase, bbase, aoff, boff, c);
        __syncthreads();    // consumption done before next STS overwrites
        if (ch + 1 < nc) {
            unsigned* nA = (unsigned*)SM + (((ch + 1) & 1) ? 2*TILEW : 0);
            stage_f32(nA, A, lda, rbase, (ch + 1) << 6, Ktot, t);
        }
    }
}

// ---------------- pred: 128x128 tile, resident B, p1 then p2, min over P=8 ----------------
__global__ __launch_bounds__(256) void k_pred_mma(const float* __restrict__ p1,
                                                  const float* __restrict__ p2,
                                                  const int* __restrict__ c1p,
                                                  const int* __restrict__ c2p,
                                                  const float* __restrict__ bpred) {
    extern __shared__ unsigned dsm[];
    const int t = threadIdx.x, lane = t & 31, warp = t >> 5;
    const int wm = warp >> 1, wn = warp & 1;
    const int rbase = blockIdx.x * 128;
    const int qc = lane & 3;

    const unsigned sm0 = (unsigned)__cvta_generic_to_shared(dsm);
    const unsigned bb0 = sm0 + TILEW * 4;
    unsigned aoff[2], boff[4];
    frag_offs(lane, wm, wn, aoff, boff);

    stage_async(bb0, g_Wpb, 64, 0, 0, 64, t);           // B staged ONCE
    cp_commit();

#pragma unroll 1
    for (int s = 0; s < 2; s++) {
        const float* preds = s ? p2 : p1;
        const int* cond = s ? c2p : c1p;
        const int xoff = s ? 256 : 128;

        stage_f32(dsm, preds, 64, rbase, 0, 64, t);     // A (fused fp32->bf16)
        if (s == 0) cp_wait<0>();
        __syncthreads();

        float c[2][8][4];
#pragma unroll
        for (int mt = 0; mt < 2; mt++)
#pragma unroll
            for (int nt = 0; nt < 8; nt++)
#pragma unroll
                for (int j = 0; j < 4; j++) c[mt][nt][j] = 0.f;
        mma_chunk(sm0, bb0, aoff, boff, c);
        __syncthreads();                                // before next s overwrites A

#pragma unroll
        for (int mt = 0; mt < 2; mt++)
#pragma unroll
            for (int nt = 0; nt < 8; nt++)
#pragma unroll
                for (int j = 0; j < 4; j++) {
                    float v = c[mt][nt][j];
                    v = fminf(v, __shfl_xor_sync(0xffffffffu, v, 4));
                    v = fminf(v, __shfl_xor_sync(0xffffffffu, v, 8));
                    v = fminf(v, __shfl_xor_sync(0xffffffffu, v, 16));
                    c[mt][nt][j] = v;
                }
        if (lane < 4) {
#pragma unroll
            for (int mt = 0; mt < 2; mt++) {
                int or0 = (rbase + wm * 32 + mt * 16) >> 3;
                float cnd0 = (float)cond[or0];
                float cnd1 = (float)cond[or0 + 1];
#pragma unroll
                for (int nt = 0; nt < 8; nt++) {
                    int col = wn * 64 + nt * 8 + qc * 2;
                    float b0 = bpred[col], b1 = bpred[col + 1];
                    unsigned w0 = pack2((c[mt][nt][0] + b0) * cnd0, (c[mt][nt][1] + b1) * cnd0);
                    *(unsigned*)&PTR_XB[(size_t)or0 * XK + xoff + col] = w0;
                    unsigned w1 = pack2((c[mt][nt][2] + b0) * cnd1, (c[mt][nt][3] + b1) * cnd1);
                    *(unsigned*)&PTR_XB[(size_t)(or0 + 1) * XK + xoff + col] = w1;
                }
            }
        }
    }
}

// ---------------- bitmap: fused fp32->bf16 A-staging ----------------
__global__ __launch_bounds__(256) void k_bm_mma(const float* __restrict__ bm,
                                                const float* __restrict__ bbm,
                                                const int* __restrict__ hc) {
    extern __shared__ unsigned dsm[];
    const int t = threadIdx.x, lane = t & 31, warp = t >> 5;
    const int wm = warp >> 1, wn = warp & 1;
    const int rbase = blockIdx.x * 128;
    float c[2][8][4];
    mm_f32A(bm, BMV, g_Wbmb, BMV, BMV, rbase, 0, dsm, t, wm, wn, lane, c);

    const int qr = lane >> 2, qc = lane & 3;
#pragma unroll
    for (int mt = 0; mt < 2; mt++)
#pragma unroll
        for (int h = 0; h < 2; h++) {
            int r = rbase + wm * 32 + mt * 16 + qr + h * 8;
            float has = (float)hc[r];
#pragma unroll
            for (int nt = 0; nt < 8; nt++) {
                int col = wn * 64 + nt * 8 + qc * 2;
                unsigned w = pack2((c[mt][nt][2*h]   + bbm[col])   * has,
                                   (c[mt][nt][2*h+1] + bbm[col+1]) * has);
                *(unsigned*)&PTR_XB[(size_t)r * XK + 384 + col] = w;
            }
        }
}

// ---------------- gi (bf16 x from pool) ----------------
__global__ __launch_bounds__(256) void k_gi_mma(const float* __restrict__ bih) {
    extern __shared__ unsigned dsm[];
    const int t = threadIdx.x, lane = t & 31, warp = t >> 5;
    const int wm = warp >> 1, wn = warp & 1;
    const int rbase = blockIdx.x * 128;
    const int cbase = blockIdx.y * 128;
    float c[2][8][4];
    mm_async(PTR_XB, XK, g_Wihb, XK, XK, rbase, cbase, dsm, t, wm, wn, lane, c);

    const int qr = lane >> 2, qc = lane & 3;
#pragma unroll
    for (int mt = 0; mt < 2; mt++)
#pragma unroll
        for (int h = 0; h < 2; h++) {
            int r = rbase + wm * 32 + mt * 16 + qr + h * 8;
            int n = r % Nn, b = r / Nn;
            size_t obase = ((size_t)n * Bsz + b) * G3;
#pragma unroll
            for (int nt = 0; nt < 8; nt++) {
                int g = cbase + wn * 64 + nt * 8 + qc * 2;
                float2 w = make_float2(c[mt][nt][2*h] + bih[g],
                                       c[mt][nt][2*h+1] + bih[g+1]);
                *(float2*)&PTR_GI[obase + g] = w;
            }
        }
}

// ---------------- gh: per-level gh[node][b][g] = 0.5(Hl+Hr) @ Whh^T ----------------
__global__ __launch_bounds__(256) void k_gh_mma(const int* __restrict__ li,
                                                const int* __restrict__ ri,
                                                int level) {
    extern __shared__ unsigned dsm[];
    const int slot = blockIdx.z;
    if (slot >= g_levcnt[level]) return;
    const int node = g_levels[level*32 + slot];
    const int l = li[node], r = ri[node];
    const int t = threadIdx.x, lane = t & 31, warp = t >> 5;
    const int wm = warp >> 1, wn = warp & 1;
    const int rbase = blockIdx.x * 128;
    const int cbase = blockIdx.y * 128;
    const float* Hl = PTR_H + (size_t)l * Bsz * HID;
    const float* Hr = PTR_H + (size_t)r * Bsz * HID;

    float c[2][8][4];
#pragma unroll
    for (int mt = 0; mt < 2; mt++)
#pragma unroll
        for (int nt = 0; nt < 8; nt++)
#pragma unroll
            for (int j = 0; j < 4; j++) c[mt][nt][j] = 0.f;

    unsigned aoff[2], boff[4];
    frag_offs(lane, wm, wn, aoff, boff);
    const unsigned sm0 = (unsigned)__cvta_generic_to_shared(dsm);
    const unsigned TB = TILEW * 4;

    for (int ch = 0; ch < 2; ch++) {
        stage_f32avg(dsm, Hl, Hr, HID, rbase, ch * 64, t);
        stage_copy(dsm + TILEW, g_Whhb, HID, cbase, ch * 64, t);
        __syncthreads();
        mma_chunk(sm0, sm0 + TB, aoff, boff, c);
        __syncthreads();
    }

    const int qr = lane >> 2, qc = lane & 3;
#pragma unroll
    for (int mt = 0; mt < 2; mt++)
#pragma unroll
        for (int h = 0; h < 2; h++) {
            int b = rbase + wm * 32 + mt * 16 + qr + h * 8;
            size_t obase = ((size_t)node * Bsz + b) * G3;
#pragma unroll
            for (int nt = 0; nt < 8; nt++) {
                int g = cbase + wn * 64 + nt * 8 + qc * 2;
                float2 w = make_float2(c[mt][nt][2*h], c[mt][nt][2*h+1]);
                *(float2*)&PTR_GH[obase + g] = w;
            }
        }
}

// ---------------- gate: elementwise GRU cell per level ----------------
__global__ __launch_bounds__(256) void k_gate(const int* __restrict__ li,
                                              const int* __restrict__ ri,
                                              const float* __restrict__ bhh,
                                              int level) {
    const int slot = blockIdx.y;
    if (slot >= g_levcnt[level]) return;
    const int node = g_levels[level*32 + slot];
    const int l = li[node], r = ri[node];
    const int idx = blockIdx.x * 256 + threadIdx.x;
    const int b = idx >> 7, g = idx & 127;
    const size_t gib = ((size_t)node * Bsz + b) * G3;
    const float br = bhh[g], bz = bhh[128+g], bn = bhh[256+g];
    float hv, ghr, ghz, ghn;
    if (l < 0) {
        hv = 0.f; ghr = br; ghz = bz; ghn = bn;
    } else {
        hv = 0.5f * (PTR_H[(size_t)l*Bsz*HID + b*HID + g] + PTR_H[(size_t)r*Bsz*HID + b*HID + g]);
        ghr = PTR_GH[gib + g] + br;
        ghz = PTR_GH[gib + 128 + g] + bz;
        ghn = PTR_GH[gib + 256 + g] + bn;
    }
    float rg = 1.f/(1.f + expf(-(PTR_GI[gib + g] + ghr)));
    float zg = 1.f/(1.f + expf(-(PTR_GI[gib + 128 + g] + ghz)));
    float ng = tanhf(PTR_GI[gib + 256 + g] + rg * ghn);
    PTR_H[((size_t)node * Bsz + b) * HID + g] = (1.f - zg) * ng + zg * hv;
}

// ---------------- opemb (fp32, small) -> bf16 x ----------------
__global__ __launch_bounds__(256) void k_opemb(const float* __restrict__ op,
                                               const float* __restrict__ ex,
                                               const float* __restrict__ bop) {
    __shared__ float As[16][68];
    __shared__ float Bs[16][128];
    const int t = threadIdx.x;
    const int rbase = blockIdx.x * 64;
    const int ty = t >> 5, tx = t & 31;
    const int row0 = ty * 8, col0 = tx * 4;
    float acc[8][4];
#pragma unroll
    for (int i = 0; i < 8; i++)
#pragma unroll
        for (int j = 0; j < 4; j++) acc[i][j] = 0.f;

    for (int kt = 0; kt < 96; kt += 16) {
#pragma unroll
        for (int i = 0; i < 4; i++) {
            int idx = t + i * 256;
            int row = idx >> 4, kk = idx & 15;
            int k = kt + kk;
            As[kk][row] = (k < 32) ? op[(size_t)(rbase+row)*32 + k]
                                   : ex[(size_t)(rbase+row)*64 + (k-32)];
        }
#pragma unroll
        for (int i = 0; i < 8; i++) {
            int idx = t + i * 256;
            int kk = idx >> 7, c = idx & 127;
            Bs[kk][c] = g_WopT[(kt+kk)*128 + c];
        }
        __syncthreads();
#pragma unroll
        for (int kk = 0; kk < 16; kk++) {
            float4 a0 = *(const float4*)&As[kk][row0];
            float4 a1 = *(const float4*)&As[kk][row0+4];
            float4 b  = *(const float4*)&Bs[kk][col0];
            float a[8] = {a0.x,a0.y,a0.z,a0.w,a1.x,a1.y,a1.z,a1.w};
            float bb[4]= {b.x,b.y,b.z,b.w};
#pragma unroll
            for (int i = 0; i < 8; i++)
#pragma unroll
                for (int j = 0; j < 4; j++) acc[i][j] += a[i]*bb[j];
        }
        __syncthreads();
    }
#pragma unroll
    for (int i = 0; i < 8; i++) {
        int r = rbase + row0 + i;
#pragma unroll
        for (int j = 0; j < 4; j += 2) {
            unsigned w = pack2(acc[i][j] + bop[col0+j], acc[i][j+1] + bop[col0+j+1]);
            *(unsigned*)&PTR_XB[(size_t)r*XK + col0 + j] = w;
        }
    }
}

// ---------------- heads ----------------
__global__ __launch_bounds__(128) void k_heads(const float* __restrict__ W2a, const float* __restrict__ b2a,
                                               const float* __restrict__ W3a, const float* __restrict__ b3a,
                                               const float* __restrict__ Woa, const float* __restrict__ boa,
                                               const float* __restrict__ W2b, const float* __restrict__ b2b,
                                               const float* __restrict__ W3b, const float* __restrict__ b3b,
                                               const float* __restrict__ Wob, const float* __restrict__ bob,
                                               float* __restrict__ out) {
    const int b = blockIdx.x, head = blockIdx.y, t = threadIdx.x;
    const float* W2 = head ? W2b : W2a;  const float* b2 = head ? b2b : b2a;
    const float* W3 = head ? W3b : W3a;  const float* b3 = head ? b3b : b3a;
    const float* Wo = head ? Wob : Woa;  const float* bo = head ? bob : boa;

    __shared__ float s0[128], s1[128], red[4];
    s0[t] = PTR_H[((size_t)(Nn-1)*Bsz + b)*HID + t];
    __syncthreads();
    float acc = b2[t];
#pragma unroll 8
    for (int k = 0; k < 128; k++) acc += s0[k] * W2[t*128 + k];
    s1[t] = fmaxf(acc, 0.f);
    __syncthreads();
    acc = b3[t];
#pragma unroll 8
    for (int k = 0; k < 128; k++) acc += s1[k] * W3[t*128 + k];
    float h2 = fmaxf(acc, 0.f);
    float v = h2 * Wo[t];
#pragma unroll
    for (int off = 16; off; off >>= 1) v += __shfl_down_sync(0xffffffffu, v, off);
    if ((t & 31) == 0) red[t >> 5] = v;
    __syncthreads();
    if (t == 0) {
        float s = red[0] + red[1] + red[2] + red[3] + bo[0];
        out[head * Bsz + b] = 1.f/(1.f + expf(-s));
    }
}

// ---------------- launcher ----------------
extern "C" void kernel_launch(void* const* d_in, const int* in_sizes, int n_in,
                              void* d_out, int out_size) {
    const float* op    = (const float*)d_in[0];
    const float* ex    = (const float*)d_in[1];
    const float* p1    = (const float*)d_in[2];
    const float* p2    = (const float*)d_in[3];
    const int*   c1p   = (const int*)  d_in[4];
    const int*   c2p   = (const int*)  d_in[5];
    const int*   hc    = (const int*)  d_in[6];
    const float* bmp   = (const float*)d_in[7];
    const int*   li    = (const int*)  d_in[8];
    const int*   ri    = (const int*)  d_in[9];
    const float* Wop   = (const float*)d_in[10];
    const float* bop   = (const float*)d_in[11];
    const float* Wpred = (const float*)d_in[12];
    const float* bpred = (const float*)d_in[13];
    const float* Wbm   = (const float*)d_in[14];
    const float* bbm   = (const float*)d_in[15];
    const float* Wih   = (const float*)d_in[16];
    const float* bih   = (const float*)d_in[17];
    const float* Whh   = (const float*)d_in[18];
    const float* bhh   = (const float*)d_in[19];
    const float* W2t1  = (const float*)d_in[20];
    const float* b2t1  = (const float*)d_in[21];
    const float* W3t1  = (const float*)d_in[22];
    const float* b3t1  = (const float*)d_in[23];
    const float* Wot1  = (const float*)d_in[24];
    const float* bot1  = (const float*)d_in[25];
    const float* W2t2  = (const float*)d_in[26];
    const float* b2t2  = (const float*)d_in[27];
    const float* W3t2  = (const float*)d_in[28];
    const float* b3t2  = (const float*)d_in[29];
    const float* Wot2  = (const float*)d_in[30];
    const float* bot2  = (const float*)d_in[31];
    float* out = (float*)d_out;

    cudaFuncSetAttribute(k_pred_mma, cudaFuncAttributeMaxDynamicSharedMemorySize, PRED_SMEM);
    cudaFuncSetAttribute(k_bm_mma,   cudaFuncAttributeMaxDynamicSharedMemorySize, DSMEM_BYTES);
    cudaFuncSetAttribute(k_gi_mma,   cudaFuncAttributeMaxDynamicSharedMemorySize, DSMEM_BYTES);
    cudaFuncSetAttribute(k_gh_mma,   cudaFuncAttributeMaxDynamicSharedMemorySize, GH_SMEM);

    k_prep<<<1540, 256>>>(Wop, Wpred, Wbm, Wih, Whh);
    k_depth<<<1, 1>>>(li);
    k_opemb<<<Rr/64, 256>>>(op, ex, bop);
    k_pred_mma<<<(Rr*8)/128, 256, PRED_SMEM>>>(p1, p2, c1p, c2p, bpred);
    k_bm_mma<<<Rr/128, 256, DSMEM_BYTES>>>(bmp, bbm, hc);
    k_gi_mma<<<dim3(Rr/128, 3), 256, DSMEM_BYTES>>>(bih);
    k_gate<<<dim3(512, 32), 256>>>(li, ri, bhh, 1);
    for (int lvl = 2; lvl <= 6; lvl++) {
        k_gh_mma<<<dim3(8, 3, 16), 256, GH_SMEM>>>(li, ri, lvl);
        k_gate<<<dim3(512, 16), 256>>>(li, ri, bhh, lvl);
    }
    k_heads<<<dim3(Bsz, 2), 128>>>(W2t1, b2t1, W3t1, b3t1, Wot1, bot1,
                                   W2t2, b2t2, W3t2, b3t2, Wot2, bot2, out);
}

// round 14
// speedup vs baseline: 1.1330x; 1.0344x over previous
#include <cuda_runtime.h>
#include <cuda_bf16.h>
#include <math.h>

#define Bsz 1024
#define Nn  63
#define Rr  (Bsz*Nn)      // 64512
#define HID 128
#define G3  384
#define XK  512
#define BMV 1000

#define SMW 36            // words per smem row (32 data words = 64 bf16 + 4 pad)
#define TILEW (128*SMW)   // words per 128-row tile
#define DSMEM_BYTES (4*TILEW*4)   // 2 buffers x (A+B) tiles = 72KB
#define GH_SMEM (2*TILEW*4)       // 1 buffer x (A+B) = 36KB

#define BM_BLKS  (Rr/128)         // 504
#define OPE_BLKS (Rr/64)          // 1008
#define PRED_BLKS ((Rr*8/128)*2)  // 8064
#define EMB_BLKS (BM_BLKS + OPE_BLKS + PRED_BLKS)

// ---------------- aliased scratch pool (phase-disjoint lifetimes) ----------------
#define OFF_GI  ((size_t)0)
#define OFF_GH  ((size_t)132120576)
#define OFF_XB  ((size_t)261144576)
#define OFF_H   ((size_t)327204864)
#define POOL_BYTES ((size_t)360235008)

__device__ __align__(128) unsigned char g_pool[POOL_BYTES];

#define PTR_GI  ((float*)(g_pool + OFF_GI))
#define PTR_GH  ((float*)(g_pool + OFF_GH))
#define PTR_XB  ((__nv_bfloat16*)(g_pool + OFF_XB))
#define PTR_H   ((float*)(g_pool + OFF_H))

__device__ __align__(16) float g_WopT [96*128];
__device__ __align__(16) __nv_bfloat16 g_Wpb  [128*64];
__device__ __align__(16) __nv_bfloat16 g_Wbmb [128*BMV];
__device__ __align__(16) __nv_bfloat16 g_Wihb [G3*XK];
__device__ __align__(16) __nv_bfloat16 g_Whhb [G3*HID];
__device__ int g_levels[8*32];
__device__ int g_levcnt[8];

// ---------------- prep: transpose Wop (fp32) + convert weights to bf16 ----------------
__global__ void k_prep(const float* __restrict__ Wop, const float* __restrict__ Wpred,
                       const float* __restrict__ Wbm, const float* __restrict__ Wih,
                       const float* __restrict__ Whh) {
    int i = blockIdx.x * blockDim.x + threadIdx.x;
    if (i < 128*96) { int r=i/96, c=i-r*96; g_WopT[c*128+r] = Wop[i]; return; }
    i -= 128*96;
    if (i < 128*64)   { g_Wpb[i]   = __float2bfloat16(Wpred[i]); return; }
    i -= 128*64;
    if (i < 128*BMV)  { g_Wbmb[i]  = __float2bfloat16(Wbm[i]);   return; }
    i -= 128*BMV;
    if (i < G3*XK)    { g_Wihb[i]  = __float2bfloat16(Wih[i]);   return; }
    i -= G3*XK;
    if (i < G3*HID)   { g_Whhb[i]  = __float2bfloat16(Whh[i]);   return; }
}

__global__ void k_depth(const int* __restrict__ li) {
    if (threadIdx.x == 0 && blockIdx.x == 0) {
        int depth[Nn];
        for (int d = 0; d < 8; d++) g_levcnt[d] = 0;
        for (int i = 0; i < Nn; i++) {
            int l = li[i];
            depth[i] = (l < 0) ? 1 : (depth[l] + 1);
            int d = depth[i];
            g_levels[d*32 + g_levcnt[d]] = i;
            g_levcnt[d]++;
        }
    }
}

// ================= bf16 MMA machinery =================
__device__ __forceinline__ unsigned pack2(float lo, float hi) {
    __nv_bfloat162 h = __floats2bfloat162_rn(lo, hi);
    return *(unsigned*)&h;
}

__device__ __forceinline__ void mma_bf16(float c[4], unsigned a0, unsigned a1,
                                         unsigned a2, unsigned a3,
                                         unsigned b0, unsigned b1) {
    asm volatile("mma.sync.aligned.m16n8k16.row.col.f32.bf16.bf16.f32 "
                 "{%0,%1,%2,%3}, {%4,%5,%6,%7}, {%8,%9}, {%0,%1,%2,%3};"
                 : "+f"(c[0]), "+f"(c[1]), "+f"(c[2]), "+f"(c[3])
                 : "r"(a0), "r"(a1), "r"(a2), "r"(a3), "r"(b0), "r"(b1));
}

__device__ __forceinline__ void ldsm4(unsigned addr, unsigned &r0, unsigned &r1,
                                      unsigned &r2, unsigned &r3) {
    asm volatile("ldmatrix.sync.aligned.m8n8.x4.shared.b16 {%0,%1,%2,%3}, [%4];"
                 : "=r"(r0), "=r"(r1), "=r"(r2), "=r"(r3) : "r"(addr));
}

__device__ __forceinline__ void cp16(unsigned dst, const void* src, int src_bytes) {
    asm volatile("cp.async.cg.shared.global [%0], [%1], 16, %2;\n"
                 :: "r"(dst), "l"(src), "r"(src_bytes));
}
__device__ __forceinline__ void cp_commit() {
    asm volatile("cp.async.commit_group;\n" ::: "memory");
}
template<int N> __device__ __forceinline__ void cp_wait() {
    asm volatile("cp.async.wait_group %0;\n" :: "n"(N) : "memory");
}

// per-lane ldmatrix byte offsets within a tile
__device__ __forceinline__ void frag_offs(int lane, int wm, int wn,
                                          unsigned aoff[2], unsigned boff[4]) {
    int g = lane >> 3, ri = lane & 7;
#pragma unroll
    for (int mt = 0; mt < 2; mt++) {
        int row = wm*32 + mt*16 + (g & 1)*8 + ri;
        aoff[mt] = row * (SMW*4) + (g >> 1) * 16;
    }
#pragma unroll
    for (int p = 0; p < 4; p++) {
        int row = wn*64 + p*16 + (g >> 1)*8 + ri;
        boff[p] = row * (SMW*4) + (g & 1) * 16;
    }
}

// consume one 64-k chunk: 4 k16 steps
__device__ __forceinline__ void mma_chunk(unsigned abase, unsigned bbase,
                                          const unsigned aoff[2], const unsigned boff[4],
                                          float c[2][8][4]) {
#pragma unroll
    for (int ks = 0; ks < 4; ks++) {
        unsigned a[2][4];
#pragma unroll
        for (int mt = 0; mt < 2; mt++)
            ldsm4(abase + aoff[mt] + ks*32, a[mt][0], a[mt][1], a[mt][2], a[mt][3]);
#pragma unroll
        for (int p = 0; p < 4; p++) {
            unsigned b0, b1, b2, b3;
            ldsm4(bbase + boff[p] + ks*32, b0, b1, b2, b3);
            mma_bf16(c[0][2*p],   a[0][0], a[0][1], a[0][2], a[0][3], b0, b1);
            mma_bf16(c[1][2*p],   a[1][0], a[1][1], a[1][2], a[1][3], b0, b1);
            mma_bf16(c[0][2*p+1], a[0][0], a[0][1], a[0][2], a[0][3], b2, b3);
            mma_bf16(c[1][2*p+1], a[1][0], a[1][1], a[1][2], a[1][3], b2, b3);
        }
    }
}

// async stage: 128 rows x 64 k (bf16 source) via cp.async
__device__ __forceinline__ void stage_async(unsigned sbase,
                                            const __nv_bfloat16* __restrict__ A,
                                            int ld, int rbase, int kt, int Ktot, int t) {
    const int row = t >> 1;
    const int seg0 = (t & 1) * 4;
    const __nv_bfloat16* rowp = A + (size_t)(rbase + row) * ld;
#pragma unroll
    for (int i = 0; i < 4; i++) {
        int k0 = kt + (seg0 + i) * 8;
        int sb = (Ktot - k0) * 2;
        sb = sb < 0 ? 0 : (sb > 16 ? 16 : sb);
        cp16(sbase + row*(SMW*4) + (seg0 + i)*16, rowp + (sb > 0 ? k0 : 0), sb);
    }
}

// register stage: 128 rows of fp32, packed to bf16 words, k-guarded
__device__ __forceinline__ void stage_f32(unsigned* S, const float* __restrict__ A,
                                          int ld, int rbase, int kt, int Ktot, int t) {
    const int tr = t >> 3, wg = t & 7;
#pragma unroll
    for (int p = 0; p < 4; p++) {
        int row = p * 32 + tr;
        size_t off = (size_t)(rbase + row) * ld + kt + wg * 8;
        int k0 = kt + wg * 8;
        uint4 w;
        if (k0 + 8 <= Ktot) {
            float4 v0 = *(const float4*)(A + off);
            float4 v1 = *(const float4*)(A + off + 4);
            w.x = pack2(v0.x, v0.y); w.y = pack2(v0.z, v0.w);
            w.z = pack2(v1.x, v1.y); w.w = pack2(v1.z, v1.w);
        } else {
            float f[8];
#pragma unroll
            for (int i = 0; i < 8; i++)
                f[i] = (k0 + i < Ktot) ? A[off + i] : 0.f;
            w.x = pack2(f[0], f[1]); w.y = pack2(f[2], f[3]);
            w.z = pack2(f[4], f[5]); w.w = pack2(f[6], f[7]);
        }
        *(uint4*)&S[row * SMW + wg * 4] = w;
    }
}

// register stage: 128 rows of fp32 avg(A,A2), packed bf16 (full 64-k chunk)
__device__ __forceinline__ void stage_f32avg(unsigned* S, const float* __restrict__ A,
                                             const float* __restrict__ A2,
                                             int ld, int rbase, int kt, int t) {
    const int tr = t >> 3, wg = t & 7;
#pragma unroll
    for (int p = 0; p < 4; p++) {
        int row = p * 32 + tr;
        size_t off = (size_t)(rbase + row) * ld + kt + wg * 8;
        float4 v0 = *(const float4*)(A + off);
        float4 v1 = *(const float4*)(A + off + 4);
        float4 u0 = *(const float4*)(A2 + off);
        float4 u1 = *(const float4*)(A2 + off + 4);
        uint4 w;
        w.x = pack2(0.5f*(v0.x+u0.x), 0.5f*(v0.y+u0.y));
        w.y = pack2(0.5f*(v0.z+u0.z), 0.5f*(v0.w+u0.w));
        w.z = pack2(0.5f*(v1.x+u1.x), 0.5f*(v1.y+u1.y));
        w.w = pack2(0.5f*(v1.z+u1.z), 0.5f*(v1.w+u1.w));
        *(uint4*)&S[row * SMW + wg * 4] = w;
    }
}

// copy stage for bf16 weights (full 64-k chunks only)
__device__ __forceinline__ void stage_copy(unsigned* S, const __nv_bfloat16* __restrict__ B,
                                           int ld, int rbase, int kt, int t) {
    const int row = t >> 1;
    const int seg0 = (t & 1) * 4;
    const __nv_bfloat16* rowp = B + (size_t)(rbase + row) * ld + kt;
#pragma unroll
    for (int i = 0; i < 4; i++)
        *(uint4*)&S[row * SMW + (seg0 + i) * 4] = *(const uint4*)(rowp + (seg0 + i) * 8);
}

// mainloop: both operands bf16, cp.async double-buffered
__device__ __forceinline__ void mm_async(const __nv_bfloat16* __restrict__ A, int lda,
                                         const __nv_bfloat16* __restrict__ B, int ldb,
                                         int Ktot, int rbase, int cbase,
                                         unsigned* SM, int t, int wm, int wn, int lane,
                                         float c[2][8][4]) {
#pragma unroll
    for (int mt = 0; mt < 2; mt++)
#pragma unroll
        for (int nt = 0; nt < 8; nt++)
#pragma unroll
            for (int j = 0; j < 4; j++) c[mt][nt][j] = 0.f;

    const unsigned sm0 = (unsigned)__cvta_generic_to_shared(SM);
    const unsigned TB = TILEW * 4;
    const int nc = (Ktot + 63) >> 6;
    unsigned aoff[2], boff[4];
    frag_offs(lane, wm, wn, aoff, boff);

    stage_async(sm0, A, lda, rbase, 0, Ktot, t);
    stage_async(sm0 + TB, B, ldb, cbase, 0, Ktot, t);
    cp_commit();

    for (int ch = 0; ch < nc; ch++) {
        unsigned abase = sm0 + (unsigned)(ch & 1) * 2 * TB;
        unsigned bbase = abase + TB;
        if (ch + 1 < nc) {
            unsigned na = sm0 + (unsigned)((ch + 1) & 1) * 2 * TB;
            stage_async(na, A, lda, rbase, (ch + 1) << 6, Ktot, t);
            stage_async(na + TB, B, ldb, cbase, (ch + 1) << 6, Ktot, t);
            cp_commit();
            cp_wait<1>();
        } else {
            cp_wait<0>();
        }
        __syncthreads();
        mma_chunk(abase, bbase, aoff, boff, c);
        __syncthreads();
    }
}

// mainloop: A fp32 (register-staged, fused convert), B bf16 (cp.async), double-buffered
__device__ __forceinline__ void mm_f32A(const float* __restrict__ A, int lda,
                                        const __nv_bfloat16* __restrict__ B, int ldb,
                                        int Ktot, int rbase, int cbase,
                                        unsigned* SM, int t, int wm, int wn, int lane,
                                        float c[2][8][4]) {
#pragma unroll
    for (int mt = 0; mt < 2; mt++)
#pragma unroll
        for (int nt = 0; nt < 8; nt++)
#pragma unroll
            for (int j = 0; j < 4; j++) c[mt][nt][j] = 0.f;

    const unsigned sm0 = (unsigned)__cvta_generic_to_shared(SM);
    const unsigned TB = TILEW * 4;
    const int nc = (Ktot + 63) >> 6;
    unsigned aoff[2], boff[4];
    frag_offs(lane, wm, wn, aoff, boff);

    stage_async(sm0 + TB, B, ldb, cbase, 0, Ktot, t);   // B0
    cp_commit();
    stage_f32(SM, A, lda, rbase, 0, Ktot, t);           // A0 (regs->STS)

    for (int ch = 0; ch < nc; ch++) {
        unsigned abase = sm0 + (unsigned)(ch & 1) * 2 * TB;
        unsigned bbase = abase + TB;
        if (ch + 1 < nc) {
            unsigned na = sm0 + (unsigned)((ch + 1) & 1) * 2 * TB;
            stage_async(na + TB, B, ldb, cbase, (ch + 1) << 6, Ktot, t);
            cp_commit();
            cp_wait<1>();   // B(ch) landed
        } else {
            cp_wait<0>();
        }
        __syncthreads();    // A(ch) STS visible, buffers free
        mma_chunk(abase, bbase, aoff, boff, c);
        __syncthreads();    // consumption done before next STS overwrites
        if (ch + 1 < nc) {
            unsigned* nA = (unsigned*)SM + (((ch + 1) & 1) ? 2*TILEW : 0);
            stage_f32(nA, A, lda, rbase, (ch + 1) << 6, Ktot, t);
        }
    }
}

// ================= fused embedding kernel: bm | opemb | pred roles =================

__device__ __forceinline__ void bm_role(int bid, const float* __restrict__ bm,
                                        const float* __restrict__ bbm,
                                        const int* __restrict__ hc, unsigned* dsm) {
    const int t = threadIdx.x, lane = t & 31, warp = t >> 5;
    const int wm = warp >> 1, wn = warp & 1;
    const int rbase = bid * 128;
    float c[2][8][4];
    mm_f32A(bm, BMV, g_Wbmb, BMV, BMV, rbase, 0, dsm, t, wm, wn, lane, c);

    const int qr = lane >> 2, qc = lane & 3;
#pragma unroll
    for (int mt = 0; mt < 2; mt++)
#pragma unroll
        for (int h = 0; h < 2; h++) {
            int r = rbase + wm * 32 + mt * 16 + qr + h * 8;
            float has = (float)hc[r];
#pragma unroll
            for (int nt = 0; nt < 8; nt++) {
                int col = wn * 64 + nt * 8 + qc * 2;
                unsigned w = pack2((c[mt][nt][2*h]   + bbm[col])   * has,
                                   (c[mt][nt][2*h+1] + bbm[col+1]) * has);
                *(unsigned*)&PTR_XB[(size_t)r * XK + 384 + col] = w;
            }
        }
}

__device__ __forceinline__ void pred_role(int bid, const float* __restrict__ p1,
                                          const float* __restrict__ p2,
                                          const int* __restrict__ c1p,
                                          const int* __restrict__ c2p,
                                          const float* __restrict__ bpred, unsigned* dsm) {
    const int py = bid & 1;
    const float* preds = py ? p2 : p1;
    const int* cond = py ? c2p : c1p;
    const int xoff = py ? 256 : 128;
    const int t = threadIdx.x, lane = t & 31, warp = t >> 5;
    const int wm = warp >> 1, wn = warp & 1;
    const int rbase = (bid >> 1) * 128;
    const int qc = lane & 3;

    const unsigned sm0 = (unsigned)__cvta_generic_to_shared(dsm);
    const unsigned bb0 = sm0 + TILEW * 4;
    unsigned aoff[2], boff[4];
    frag_offs(lane, wm, wn, aoff, boff);

    stage_async(bb0, g_Wpb, 64, 0, 0, 64, t);      // B
    cp_commit();
    stage_f32(dsm, preds, 64, rbase, 0, 64, t);    // A (fused convert)
    cp_wait<0>();
    __syncthreads();

    float c[2][8][4];
#pragma unroll
    for (int mt = 0; mt < 2; mt++)
#pragma unroll
        for (int nt = 0; nt < 8; nt++)
#pragma unroll
            for (int j = 0; j < 4; j++) c[mt][nt][j] = 0.f;
    mma_chunk(sm0, bb0, aoff, boff, c);

#pragma unroll
    for (int mt = 0; mt < 2; mt++)
#pragma unroll
        for (int nt = 0; nt < 8; nt++)
#pragma unroll
            for (int j = 0; j < 4; j++) {
                float v = c[mt][nt][j];
                v = fminf(v, __shfl_xor_sync(0xffffffffu, v, 4));
                v = fminf(v, __shfl_xor_sync(0xffffffffu, v, 8));
                v = fminf(v, __shfl_xor_sync(0xffffffffu, v, 16));
                c[mt][nt][j] = v;
            }
    if (lane < 4) {
#pragma unroll
        for (int mt = 0; mt < 2; mt++) {
            int or0 = (rbase + wm * 32 + mt * 16) >> 3;
            float cnd0 = (float)cond[or0];
            float cnd1 = (float)cond[or0 + 1];
#pragma unroll
            for (int nt = 0; nt < 8; nt++) {
                int col = wn * 64 + nt * 8 + qc * 2;
                float b0 = bpred[col], b1 = bpred[col + 1];
                unsigned w0 = pack2((c[mt][nt][0] + b0) * cnd0, (c[mt][nt][1] + b1) * cnd0);
                *(unsigned*)&PTR_XB[(size_t)or0 * XK + xoff + col] = w0;
                unsigned w1 = pack2((c[mt][nt][2] + b0) * cnd1, (c[mt][nt][3] + b1) * cnd1);
                *(unsigned*)&PTR_XB[(size_t)(or0 + 1) * XK + xoff + col] = w1;
            }
        }
    }
}

__device__ __forceinline__ void opemb_role(int bid, const float* __restrict__ op,
                                           const float* __restrict__ ex,
                                           const float* __restrict__ bop, unsigned* dsm) {
    float* As = (float*)dsm;                 // [16][68]
    float* Bs = (float*)dsm + 16*68;         // [16][128]
    const int t = threadIdx.x;
    const int rbase = bid * 64;
    const int ty = t >> 5, tx = t & 31;
    const int row0 = ty * 8, col0 = tx * 4;
    float acc[8][4];
#pragma unroll
    for (int i = 0; i < 8; i++)
#pragma unroll
        for (int j = 0; j < 4; j++) acc[i][j] = 0.f;

    for (int kt = 0; kt < 96; kt += 16) {
#pragma unroll
        for (int i = 0; i < 4; i++) {
            int idx = t + i * 256;
            int row = idx >> 4, kk = idx & 15;
            int k = kt + kk;
            As[kk*68 + row] = (k < 32) ? op[(size_t)(rbase+row)*32 + k]
                                       : ex[(size_t)(rbase+row)*64 + (k-32)];
        }
#pragma unroll
        for (int i = 0; i < 8; i++) {
            int idx = t + i * 256;
            int kk = idx >> 7, c = idx & 127;
            Bs[kk*128 + c] = g_WopT[(kt+kk)*128 + c];
        }
        __syncthreads();
#pragma unroll
        for (int kk = 0; kk < 16; kk++) {
            float4 a0 = *(const float4*)&As[kk*68 + row0];
            float4 a1 = *(const float4*)&As[kk*68 + row0+4];
            float4 b  = *(const float4*)&Bs[kk*128 + col0];
            float a[8] = {a0.x,a0.y,a0.z,a0.w,a1.x,a1.y,a1.z,a1.w};
            float bb[4]= {b.x,b.y,b.z,b.w};
#pragma unroll
            for (int i = 0; i < 8; i++)
#pragma unroll
                for (int j = 0; j < 4; j++) acc[i][j] += a[i]*bb[j];
        }
        __syncthreads();
    }
#pragma unroll
    for (int i = 0; i < 8; i++) {
        int r = rbase + row0 + i;
#pragma unroll
        for (int j = 0; j < 4; j += 2) {
            unsigned w = pack2(acc[i][j] + bop[col0+j], acc[i][j+1] + bop[col0+j+1]);
            *(unsigned*)&PTR_XB[(size_t)r*XK + col0 + j] = w;
        }
    }
}

__global__ __launch_bounds__(256) void k_embed(const float* __restrict__ p1,
                                               const float* __restrict__ p2,
                                               const int* __restrict__ c1p,
                                               const int* __restrict__ c2p,
                                               const float* __restrict__ bpred,
                                               const float* __restrict__ bm,
                                               const float* __restrict__ bbm,
                                               const int* __restrict__ hc,
                                               const float* __restrict__ op,
                                               const float* __restrict__ ex,
                                               const float* __restrict__ bop) {
    extern __shared__ unsigned dsm[];
    int bid = blockIdx.x;
    if (bid < BM_BLKS) { bm_role(bid, bm, bbm, hc, dsm); return; }
    bid -= BM_BLKS;
    if (bid < OPE_BLKS) { opemb_role(bid, op, ex, bop, dsm); return; }
    bid -= OPE_BLKS;
    pred_role(bid, p1, p2, c1p, c2p, bpred, dsm);
}

// ---------------- gi (bf16 x from pool) ----------------
__global__ __launch_bounds__(256) void k_gi_mma(const float* __restrict__ bih) {
    extern __shared__ unsigned dsm[];
    const int t = threadIdx.x, lane = t & 31, warp = t >> 5;
    const int wm = warp >> 1, wn = warp & 1;
    const int rbase = blockIdx.x * 128;
    const int cbase = blockIdx.y * 128;
    float c[2][8][4];
    mm_async(PTR_XB, XK, g_Wihb, XK, XK, rbase, cbase, dsm, t, wm, wn, lane, c);

    const int qr = lane >> 2, qc = lane & 3;
#pragma unroll
    for (int mt = 0; mt < 2; mt++)
#pragma unroll
        for (int h = 0; h < 2; h++) {
            int r = rbase + wm * 32 + mt * 16 + qr + h * 8;
            int n = r % Nn, b = r / Nn;
            size_t obase = ((size_t)n * Bsz + b) * G3;
#pragma unroll
            for (int nt = 0; nt < 8; nt++) {
                int g = cbase + wn * 64 + nt * 8 + qc * 2;
                float2 w = make_float2(c[mt][nt][2*h] + bih[g],
                                       c[mt][nt][2*h+1] + bih[g+1]);
                *(float2*)&PTR_GI[obase + g] = w;
            }
        }
}

// ---------------- gh: per-level gh[node][b][g] = 0.5(Hl+Hr) @ Whh^T ----------------
__global__ __launch_bounds__(256) void k_gh_mma(const int* __restrict__ li,
                                                const int* __restrict__ ri,
                                                int level) {
    extern __shared__ unsigned dsm[];
    const int slot = blockIdx.z;
    if (slot >= g_levcnt[level]) return;
    const int node = g_levels[level*32 + slot];
    const int l = li[node], r = ri[node];
    const int t = threadIdx.x, lane = t & 31, warp = t >> 5;
    const int wm = warp >> 1, wn = warp & 1;
    const int rbase = blockIdx.x * 128;
    const int cbase = blockIdx.y * 128;
    const float* Hl = PTR_H + (size_t)l * Bsz * HID;
    const float* Hr = PTR_H + (size_t)r * Bsz * HID;

    float c[2][8][4];
#pragma unroll
    for (int mt = 0; mt < 2; mt++)
#pragma unroll
        for (int nt = 0; nt < 8; nt++)
#pragma unroll
            for (int j = 0; j < 4; j++) c[mt][nt][j] = 0.f;

    unsigned aoff[2], boff[4];
    frag_offs(lane, wm, wn, aoff, boff);
    const unsigned sm0 = (unsigned)__cvta_generic_to_shared(dsm);
    const unsigned TB = TILEW * 4;

    for (int ch = 0; ch < 2; ch++) {
        stage_f32avg(dsm, Hl, Hr, HID, rbase, ch * 64, t);
        stage_copy(dsm + TILEW, g_Whhb, HID, cbase, ch * 64, t);
        __syncthreads();
        mma_chunk(sm0, sm0 + TB, aoff, boff, c);
        __syncthreads();
    }

    const int qr = lane >> 2, qc = lane & 3;
#pragma unroll
    for (int mt = 0; mt < 2; mt++)
#pragma unroll
        for (int h = 0; h < 2; h++) {
            int b = rbase + wm * 32 + mt * 16 + qr + h * 8;
            size_t obase = ((size_t)node * Bsz + b) * G3;
#pragma unroll
            for (int nt = 0; nt < 8; nt++) {
                int g = cbase + wn * 64 + nt * 8 + qc * 2;
                float2 w = make_float2(c[mt][nt][2*h], c[mt][nt][2*h+1]);
                *(float2*)&PTR_GH[obase + g] = w;
            }
        }
}

// ---------------- gate: elementwise GRU cell per level ----------------
__global__ __launch_bounds__(256) void k_gate(const int* __restrict__ li,
                                              const int* __restrict__ ri,
                                              const float* __restrict__ bhh,
                                              int level) {
    const int slot = blockIdx.y;
    if (slot >= g_levcnt[level]) return;
    const int node = g_levels[level*32 + slot];
    const int l = li[node], r = ri[node];
    const int idx = blockIdx.x * 256 + threadIdx.x;
    const int b = idx >> 7, g = idx & 127;
    const size_t gib = ((size_t)node * Bsz + b) * G3;
    const float br = bhh[g], bz = bhh[128+g], bn = bhh[256+g];
    float hv, ghr, ghz, ghn;
    if (l < 0) {
        hv = 0.f; ghr = br; ghz = bz; ghn = bn;
    } else {
        hv = 0.5f * (PTR_H[(size_t)l*Bsz*HID + b*HID + g] + PTR_H[(size_t)r*Bsz*HID + b*HID + g]);
        ghr = PTR_GH[gib + g] + br;
        ghz = PTR_GH[gib + 128 + g] + bz;
        ghn = PTR_GH[gib + 256 + g] + bn;
    }
    float rg = 1.f/(1.f + expf(-(PTR_GI[gib + g] + ghr)));
    float zg = 1.f/(1.f + expf(-(PTR_GI[gib + 128 + g] + ghz)));
    float ng = tanhf(PTR_GI[gib + 256 + g] + rg * ghn);
    PTR_H[((size_t)node * Bsz + b) * HID + g] = (1.f - zg) * ng + zg * hv;
}

// ---------------- heads ----------------
__global__ __launch_bounds__(128) void k_heads(const float* __restrict__ W2a, const float* __restrict__ b2a,
                                               const float* __restrict__ W3a, const float* __restrict__ b3a,
                                               const float* __restrict__ Woa, const float* __restrict__ boa,
                                               const float* __restrict__ W2b, const float* __restrict__ b2b,
                                               const float* __restrict__ W3b, const float* __restrict__ b3b,
                                               const float* __restrict__ Wob, const float* __restrict__ bob,
                                               float* __restrict__ out) {
    const int b = blockIdx.x, head = blockIdx.y, t = threadIdx.x;
    const float* W2 = head ? W2b : W2a;  const float* b2 = head ? b2b : b2a;
    const float* W3 = head ? W3b : W3a;  const float* b3 = head ? b3b : b3a;
    const float* Wo = head ? Wob : Woa;  const float* bo = head ? bob : boa;

    __shared__ float s0[128], s1[128], red[4];
    s0[t] = PTR_H[((size_t)(Nn-1)*Bsz + b)*HID + t];
    __syncthreads();
    float acc = b2[t];
#pragma unroll 8
    for (int k = 0; k < 128; k++) acc += s0[k] * W2[t*128 + k];
    s1[t] = fmaxf(acc, 0.f);
    __syncthreads();
    acc = b3[t];
#pragma unroll 8
    for (int k = 0; k < 128; k++) acc += s1[k] * W3[t*128 + k];
    float h2 = fmaxf(acc, 0.f);
    float v = h2 * Wo[t];
#pragma unroll
    for (int off = 16; off; off >>= 1) v += __shfl_down_sync(0xffffffffu, v, off);
    if ((t & 31) == 0) red[t >> 5] = v;
    __syncthreads();
    if (t == 0) {
        float s = red[0] + red[1] + red[2] + red[3] + bo[0];
        out[head * Bsz + b] = 1.f/(1.f + expf(-s));
    }
}

// ---------------- launcher ----------------
extern "C" void kernel_launch(void* const* d_in, const int* in_sizes, int n_in,
                              void* d_out, int out_size) {
    const float* op    = (const float*)d_in[0];
    const float* ex    = (const float*)d_in[1];
    const float* p1    = (const float*)d_in[2];
    const float* p2    = (const float*)d_in[3];
    const int*   c1p   = (const int*)  d_in[4];
    const int*   c2p   = (const int*)  d_in[5];
    const int*   hc    = (const int*)  d_in[6];
    const float* bmp   = (const float*)d_in[7];
    const int*   li    = (const int*)  d_in[8];
    const int*   ri    = (const int*)  d_in[9];
    const float* Wop   = (const float*)d_in[10];
    const float* bop   = (const float*)d_in[11];
    const float* Wpred = (const float*)d_in[12];
    const float* bpred = (const float*)d_in[13];
    const float* Wbm   = (const float*)d_in[14];
    const float* bbm   = (const float*)d_in[15];
    const float* Wih   = (const float*)d_in[16];
    const float* bih   = (const float*)d_in[17];
    const float* Whh   = (const float*)d_in[18];
    const float* bhh   = (const float*)d_in[19];
    const float* W2t1  = (const float*)d_in[20];
    const float* b2t1  = (const float*)d_in[21];
    const float* W3t1  = (const float*)d_in[22];
    const float* b3t1  = (const float*)d_in[23];
    const float* Wot1  = (const float*)d_in[24];
    const float* bot1  = (const float*)d_in[25];
    const float* W2t2  = (const float*)d_in[26];
    const float* b2t2  = (const float*)d_in[27];
    const float* W3t2  = (const float*)d_in[28];
    const float* b3t2  = (const float*)d_in[29];
    const float* Wot2  = (const float*)d_in[30];
    const float* bot2  = (const float*)d_in[31];
    float* out = (float*)d_out;

    cudaFuncSetAttribute(k_embed, cudaFuncAttributeMaxDynamicSharedMemorySize, DSMEM_BYTES);
    cudaFuncSetAttribute(k_gi_mma, cudaFuncAttributeMaxDynamicSharedMemorySize, DSMEM_BYTES);
    cudaFuncSetAttribute(k_gh_mma, cudaFuncAttributeMaxDynamicSharedMemorySize, GH_SMEM);

    k_prep<<<1540, 256>>>(Wop, Wpred, Wbm, Wih, Whh);
    k_depth<<<1, 1>>>(li);
    k_embed<<<EMB_BLKS, 256, DSMEM_BYTES>>>(p1, p2, c1p, c2p, bpred,
                                            bmp, bbm, hc, op, ex, bop);
    k_gi_mma<<<dim3(Rr/128, 3), 256, DSMEM_BYTES>>>(bih);
    k_gate<<<dim3(512, 32), 256>>>(li, ri, bhh, 1);
    for (int lvl = 2; lvl <= 6; lvl++) {
        k_gh_mma<<<dim3(8, 3, 16), 256, GH_SMEM>>>(li, ri, lvl);
        k_gate<<<dim3(512, 16), 256>>>(li, ri, bhh, lvl);
    }
    k_heads<<<dim3(Bsz, 2), 128>>>(W2t1, b2t1, W3t1, b3t1, Wot1, bot1,
                                   W2t2, b2t2, W3t2, b3t2, Wot2, bot2, out);
}